// round 7
// baseline (speedup 1.0000x reference)
#include <cuda_runtime.h>

#define BB 32
#define TT 512
#define UU 512
#define NG 1536          // 3*U
#define OC 1024          // 2*U output channels

// x-gates scratch: [dir][B*T][3U] fp32 (192 MB, static device allocation)
__device__ float    g_xg[(size_t)2 * BB * TT * NG];
// per-step rh = r * h_prev exchange buffer
__device__ float    g_rh[2 * BB * UU];
// software grid barrier state (per direction)
__device__ unsigned g_cnt[2];
__device__ unsigned g_gen[2];

__device__ __forceinline__ float hsig(float v) {
    return fminf(fmaxf(0.2f * v + 0.5f, 0.0f), 1.0f);
}

// ---------------------------------------------------------------------------
// Phase 1: Xg[dir][m][n] = x[m][:] @ W_dir[:][n] + bias_dir[n]
// M=16384, K=512, N=1536. BM=BN=128, BK=16, 256 thr, 8x8 reg tile,
// register-prefetch double buffering (LDG for next tile overlaps FMA).
// ---------------------------------------------------------------------------
#define XS 132           // padded smem row stride (floats)

__global__ void __launch_bounds__(256, 2)
xgemm_kernel(const float* __restrict__ A,
             const float* __restrict__ Wf, const float* __restrict__ bf,
             const float* __restrict__ Wb, const float* __restrict__ bb)
{
    const int dir = blockIdx.z;
    const float* __restrict__ W    = dir ? Wb : Wf;
    const float* __restrict__ bias = dir ? bb : bf;
    const int m0 = blockIdx.y * 128;
    const int n0 = blockIdx.x * 128;

    __shared__ float As[16 * XS];   // [k][m]
    __shared__ float Bs[16 * XS];   // [k][n]

    const int tid = threadIdx.x;
    const int tx = tid & 15;        // n group (8 cols)
    const int ty = tid >> 4;        // m group (8 rows)

    // A loader: thread -> row arow, k-offset akq (two float4 = 8 k)
    const int arow = tid >> 1;             // 0..127
    const int akq  = (tid & 1) << 3;       // 0 or 8
    // B loader: thread -> k row bk, n-offset bn (two float4 = 8 n)
    const int bk = tid >> 4;               // 0..15
    const int bn = (tid & 15) << 3;        // 0..120

    const float* Aptr = A + (size_t)(m0 + arow) * 512 + akq;
    const float* Wptr = W + (size_t)bk * NG + n0 + bn;

    float acc[8][8];
#pragma unroll
    for (int i = 0; i < 8; ++i)
#pragma unroll
        for (int j = 0; j < 8; ++j) acc[i][j] = 0.0f;

    // prologue: load tile 0
    float4 a0 = *(const float4*)(Aptr + 0);
    float4 a1 = *(const float4*)(Aptr + 4);
    float4 b0 = *(const float4*)(Wptr + 0);
    float4 b1 = *(const float4*)(Wptr + 4);

    {   // store tile 0
        float av[8] = {a0.x,a0.y,a0.z,a0.w,a1.x,a1.y,a1.z,a1.w};
#pragma unroll
        for (int j = 0; j < 8; ++j) As[(akq + j) * XS + arow] = av[j];
        *(float4*)&Bs[bk * XS + bn]     = b0;
        *(float4*)&Bs[bk * XS + bn + 4] = b1;
    }
    __syncthreads();

    for (int kt = 0; kt < 32; ++kt) {
        const int k_next = (kt + 1) << 4;
        if (kt < 31) {                      // prefetch next tile into regs
            a0 = *(const float4*)(Aptr + k_next + 0);
            a1 = *(const float4*)(Aptr + k_next + 4);
            b0 = *(const float4*)(Wptr + (size_t)k_next * NG + 0);
            b1 = *(const float4*)(Wptr + (size_t)k_next * NG + 4);
        }

#pragma unroll
        for (int kk = 0; kk < 16; ++kk) {
            float4 av0 = *(const float4*)&As[kk * XS + ty * 8];
            float4 av1 = *(const float4*)&As[kk * XS + ty * 8 + 4];
            float4 bv0 = *(const float4*)&Bs[kk * XS + tx * 8];
            float4 bv1 = *(const float4*)&Bs[kk * XS + tx * 8 + 4];
            float aa[8] = {av0.x,av0.y,av0.z,av0.w,av1.x,av1.y,av1.z,av1.w};
            float bb2[8] = {bv0.x,bv0.y,bv0.z,bv0.w,bv1.x,bv1.y,bv1.z,bv1.w};
#pragma unroll
            for (int i = 0; i < 8; ++i)
#pragma unroll
                for (int j = 0; j < 8; ++j)
                    acc[i][j] = fmaf(aa[i], bb2[j], acc[i][j]);
        }

        if (kt < 31) {
            __syncthreads();
            float av[8] = {a0.x,a0.y,a0.z,a0.w,a1.x,a1.y,a1.z,a1.w};
#pragma unroll
            for (int j = 0; j < 8; ++j) As[(akq + j) * XS + arow] = av[j];
            *(float4*)&Bs[bk * XS + bn]     = b0;
            *(float4*)&Bs[bk * XS + bn + 4] = b1;
            __syncthreads();
        }
    }

    // epilogue: bias + store
    float* __restrict__ Cd = g_xg + (size_t)dir * BB * TT * NG;
    const int nbase = n0 + tx * 8;
    float4 bi0 = *(const float4*)(bias + nbase);
    float4 bi1 = *(const float4*)(bias + nbase + 4);
#pragma unroll
    for (int i = 0; i < 8; ++i) {
        const int m = m0 + ty * 8 + i;
        float4 o0, o1;
        o0.x = acc[i][0] + bi0.x; o0.y = acc[i][1] + bi0.y;
        o0.z = acc[i][2] + bi0.z; o0.w = acc[i][3] + bi0.w;
        o1.x = acc[i][4] + bi1.x; o1.y = acc[i][5] + bi1.y;
        o1.z = acc[i][6] + bi1.z; o1.w = acc[i][7] + bi1.w;
        *(float4*)&Cd[(size_t)m * NG + nbase]     = o0;
        *(float4*)&Cd[(size_t)m * NG + nbase + 4] = o1;
    }
}

// ---------------------------------------------------------------------------
// Software grid barrier: per-direction (64 blocks), monotonic generation.
// All 128 blocks co-resident (1 block/SM, 128 <= 148 SMs) => deadlock-free.
// ---------------------------------------------------------------------------
__device__ __forceinline__ void grid_bar(int dir, int tid, unsigned& bar_t)
{
    __threadfence();                       // release all threads' global writes
    __syncthreads();
    if (tid == 0) {
        ++bar_t;                           // target generation
        unsigned arrived = atomicAdd(&g_cnt[dir], 1u) + 1u;
        if (arrived == 64u) {
            atomicExch(&g_cnt[dir], 0u);
            __threadfence();
            atomicExch(&g_gen[dir], bar_t);
        } else {
            while ((int)(*(volatile unsigned*)&g_gen[dir] - bar_t) < 0) { }
            __threadfence();               // acquire
        }
    }
    __syncthreads();
}

// ---------------------------------------------------------------------------
// Phase 2: persistent scan. 128 blocks x 256 threads. Block = (dir, 8 cols).
// Thread = (batch b, column c); full K=512 in-register (no reductions).
// h / rh streamed in 4 chunks of 128 with LDG->STS double buffering so the
// L2 exchange hides under the FMA chunks.
// smem: sWz/sWr/sWh 3*8*516 = 12384 | sHa,sHb 2*32*132 = 8448  (83,328 B)
// ---------------------------------------------------------------------------
#define SWS 516          // weight row stride  (floats)
#define CHS 132          // h-chunk row stride (floats)
#define SCAN_SMEM_FLOATS (3 * 8 * SWS + 2 * BB * CHS)
#define SCAN_SMEM_BYTES  (SCAN_SMEM_FLOATS * 4)

__global__ void __launch_bounds__(256, 1)
scan_kernel(const float* __restrict__ Uf,
            const float* __restrict__ Ub,
            float* __restrict__ out)
{
    extern __shared__ float sm[];
    float* sWz = sm;                     // [c][u]  c*516 + u
    float* sWr = sWz + 8 * SWS;
    float* sWh = sWr + 8 * SWS;
    float* sHa = sWh + 8 * SWS;          // chunk buffer A [b][u127]
    float* sHb = sHa + BB * CHS;         // chunk buffer B

    const int tid   = threadIdx.x;
    const int dir   = blockIdx.x >> 6;
    const int cg    = blockIdx.x & 63;
    const int hbase = cg << 3;
    const float* __restrict__ Urec = dir ? Ub : Uf;

    // --- weight slices, loaded ONCE, transposed to [c][u] ---
    for (int i = tid; i < 4096; i += 256) {
        const int u  = i >> 3;
        const int cc = i & 7;
        const size_t src = (size_t)u * NG + hbase + cc;
        sWz[cc * SWS + u] = Urec[src];
        sWr[cc * SWS + u] = Urec[src + UU];
        sWh[cc * SWS + u] = Urec[src + 2 * UU];
    }

    unsigned bar_t = 0;
    if (tid == 0) bar_t = *(volatile unsigned*)&g_gen[dir];

    const int b = tid >> 3;              // 0..31
    const int c = tid & 7;               // 0..7
    const int j = hbase + c;

    // loader mapping: 4 float4 per thread per chunk (1024 float4 total)
    const int lb[4]  = { (tid + 0) >> 5, (tid + 256) >> 5,
                         (tid + 512) >> 5, (tid + 768) >> 5 };
    const int lu4    = (tid & 31) << 2;  // same low bits for all 4

    const size_t xg_base = (size_t)dir * BB * TT + (size_t)b * TT;
    const int    rh_base = (dir * BB) << 9;
    const size_t out_col = (size_t)dir * UU;

    const float* wzp = sWz + c * SWS;
    const float* wrp = sWr + c * SWS;
    const float* whp = sWh + c * SWS;

    __syncthreads();                     // weights ready

    for (int s = 0; s < TT; ++s) {
        // ---- prefetch x-gate values + h_prev own element ----
        const int t_x = dir ? (TT - 1 - s) : s;
        const float* __restrict__ xrow = g_xg + (xg_base + t_x) * NG;
        const float xz = xrow[j];
        const float xr = xrow[UU + j];
        const float xh = xrow[2 * UU + j];
        float hp = 0.0f;
        if (s > 0)
            hp = __ldcg(out + ((size_t)b * TT + (s - 1)) * OC + out_col + j);

        float az = 0.0f, ar = 0.0f;

        // =========== phase A: z/r gate GEMM, pipelined over 4 chunks =======
        float4 pf[4];
        // load chunk 0
#pragma unroll
        for (int r = 0; r < 4; ++r) {
            if (s == 0) pf[r] = make_float4(0.f, 0.f, 0.f, 0.f);
            else pf[r] = __ldcg((const float4*)(out +
                     ((size_t)lb[r] * TT + (s - 1)) * OC + out_col + lu4));
        }
#pragma unroll
        for (int r = 0; r < 4; ++r)
            *(float4*)&sHa[lb[r] * CHS + lu4] = pf[r];
        __syncthreads();

#pragma unroll
        for (int q = 0; q < 4; ++q) {
            if (q < 3) {                 // prefetch chunk q+1
                const int uq = (q + 1) << 7;
#pragma unroll
                for (int r = 0; r < 4; ++r) {
                    if (s == 0) pf[r] = make_float4(0.f, 0.f, 0.f, 0.f);
                    else pf[r] = __ldcg((const float4*)(out +
                         ((size_t)lb[r] * TT + (s - 1)) * OC + out_col + uq + lu4));
                }
            }
            const float* wz = wzp + (q << 7);
            const float* wr = wrp + (q << 7);
            const float* hb = ((q & 1) ? sHb : sHa) + b * CHS;
#pragma unroll 8
            for (int uu = 0; uu < 128; uu += 4) {
                float4 w1 = *(const float4*)(wz + uu);
                float4 w2 = *(const float4*)(wr + uu);
                float4 hv = *(const float4*)(hb + uu);
                az = fmaf(hv.x, w1.x, az); ar = fmaf(hv.x, w2.x, ar);
                az = fmaf(hv.y, w1.y, az); ar = fmaf(hv.y, w2.y, ar);
                az = fmaf(hv.z, w1.z, az); ar = fmaf(hv.z, w2.z, ar);
                az = fmaf(hv.w, w1.w, az); ar = fmaf(hv.w, w2.w, ar);
            }
            if (q < 3) {
                float* dst = (q & 1) ? sHa : sHb;
#pragma unroll
                for (int r = 0; r < 4; ++r)
                    *(float4*)&dst[lb[r] * CHS + lu4] = pf[r];
                __syncthreads();
            }
        }

        // ---- gate nonlinearity, publish rh ----
        float rz, rzh;
        {
            const float z = hsig(xz + az);
            const float r = hsig(xr + ar);
            rz  = z;
            rzh = z * hp;
            __stcg(&g_rh[rh_base + (b << 9) + j], r * hp);
        }
        grid_bar(dir, tid, bar_t);

        // =========== phase B: candidate GEMM over rh, pipelined ============
        float ah = 0.0f;
#pragma unroll
        for (int r = 0; r < 4; ++r)
            pf[r] = __ldcg((const float4*)(g_rh + rh_base + (lb[r] << 9) + lu4));
#pragma unroll
        for (int r = 0; r < 4; ++r)
            *(float4*)&sHa[lb[r] * CHS + lu4] = pf[r];
        __syncthreads();

#pragma unroll
        for (int q = 0; q < 4; ++q) {
            if (q < 3) {
                const int uq = (q + 1) << 7;
#pragma unroll
                for (int r = 0; r < 4; ++r)
                    pf[r] = __ldcg((const float4*)(g_rh + rh_base +
                                                   (lb[r] << 9) + uq + lu4));
            }
            const float* wh = whp + (q << 7);
            const float* hb = ((q & 1) ? sHb : sHa) + b * CHS;
#pragma unroll 8
            for (int uu = 0; uu < 128; uu += 4) {
                float4 w1 = *(const float4*)(wh + uu);
                float4 hv = *(const float4*)(hb + uu);
                ah = fmaf(hv.x, w1.x, ah);
                ah = fmaf(hv.y, w1.y, ah);
                ah = fmaf(hv.z, w1.z, ah);
                ah = fmaf(hv.w, w1.w, ah);
            }
            if (q < 3) {
                float* dst = (q & 1) ? sHa : sHb;
#pragma unroll
                for (int r = 0; r < 4; ++r)
                    *(float4*)&dst[lb[r] * CHS + lu4] = pf[r];
                __syncthreads();
            }
        }

        // ---- h_new -> out ----
        {
            const float cand = tanhf(xh + ah);
            const float hnew = rzh + (1.0f - rz) * cand;
            __stcg(&out[((size_t)b * TT + s) * OC + out_col + j], hnew);
        }
        grid_bar(dir, tid, bar_t);
    }
}

// ---------------------------------------------------------------------------
extern "C" void kernel_launch(void* const* d_in, const int* in_sizes, int n_in,
                              void* d_out, int out_size)
{
    (void)in_sizes; (void)n_in; (void)out_size;
    const float* x  = (const float*)d_in[0];
    const float* Wf = (const float*)d_in[1];
    const float* Uf = (const float*)d_in[2];
    const float* bf = (const float*)d_in[3];
    const float* Wb = (const float*)d_in[4];
    const float* Ub = (const float*)d_in[5];
    const float* bb = (const float*)d_in[6];
    float* out = (float*)d_out;

    cudaFuncSetAttribute(scan_kernel,
                         cudaFuncAttributeMaxDynamicSharedMemorySize,
                         SCAN_SMEM_BYTES);

    dim3 g1(NG / 128, (BB * TT) / 128, 2);   // 12 x 128 x 2
    xgemm_kernel<<<g1, 256>>>(x, Wf, bf, Wb, bb);

    scan_kernel<<<128, 256, SCAN_SMEM_BYTES>>>(Uf, Ub, out);
}

// round 8
// speedup vs baseline: 1.0045x; 1.0045x over previous
#include <cuda_runtime.h>

#define BB 32
#define TT 512
#define UU 512
#define NG 1536          // 3*U
#define OC 1024          // 2*U output channels

// x-gates scratch: [dir][B*T][3U] fp32 (192 MB, static device allocation)
__device__ float    g_xg[(size_t)2 * BB * TT * NG];
// per-step rh = r * h_prev exchange buffer
__device__ float    g_rh[2 * BB * UU];
// software grid barrier state (per direction)
__device__ unsigned g_cnt[2];
__device__ unsigned g_gen[2];

__device__ __forceinline__ float hsig(float v) {
    return fminf(fmaxf(0.2f * v + 0.5f, 0.0f), 1.0f);
}

// packed dual-FMA: acc.{lo,hi} += a.{lo,hi} * b.{lo,hi}
#define FMA2(acc, a, b) \
    asm("fma.rn.f32x2 %0, %1, %2, %0;" : "+l"(acc) : "l"(a), "l"(b))

__device__ __forceinline__ float pair_sum(unsigned long long v) {
    return __uint_as_float((unsigned)v) + __uint_as_float((unsigned)(v >> 32));
}

// ---------------------------------------------------------------------------
// Phase 1: Xg[dir][m][n] = x[m][:] @ W_dir[:][n] + bias_dir[n]
// M=16384, K=512, N=1536. BM=BN=128, BK=16, 256 thr, 8x8 reg tile,
// register-prefetch double buffering.
// ---------------------------------------------------------------------------
#define XS 132           // padded smem row stride (floats)

__global__ void __launch_bounds__(256, 2)
xgemm_kernel(const float* __restrict__ A,
             const float* __restrict__ Wf, const float* __restrict__ bf,
             const float* __restrict__ Wb, const float* __restrict__ bb)
{
    const int dir = blockIdx.z;
    const float* __restrict__ W    = dir ? Wb : Wf;
    const float* __restrict__ bias = dir ? bb : bf;
    const int m0 = blockIdx.y * 128;
    const int n0 = blockIdx.x * 128;

    __shared__ float As[16 * XS];   // [k][m]
    __shared__ float Bs[16 * XS];   // [k][n]

    const int tid = threadIdx.x;
    const int tx = tid & 15;        // n group (8 cols)
    const int ty = tid >> 4;        // m group (8 rows)

    const int arow = tid >> 1;             // 0..127
    const int akq  = (tid & 1) << 3;       // 0 or 8
    const int bk = tid >> 4;               // 0..15
    const int bn = (tid & 15) << 3;        // 0..120

    const float* Aptr = A + (size_t)(m0 + arow) * 512 + akq;
    const float* Wptr = W + (size_t)bk * NG + n0 + bn;

    float acc[8][8];
#pragma unroll
    for (int i = 0; i < 8; ++i)
#pragma unroll
        for (int j = 0; j < 8; ++j) acc[i][j] = 0.0f;

    float4 a0 = *(const float4*)(Aptr + 0);
    float4 a1 = *(const float4*)(Aptr + 4);
    float4 b0 = *(const float4*)(Wptr + 0);
    float4 b1 = *(const float4*)(Wptr + 4);

    {
        float av[8] = {a0.x,a0.y,a0.z,a0.w,a1.x,a1.y,a1.z,a1.w};
#pragma unroll
        for (int j = 0; j < 8; ++j) As[(akq + j) * XS + arow] = av[j];
        *(float4*)&Bs[bk * XS + bn]     = b0;
        *(float4*)&Bs[bk * XS + bn + 4] = b1;
    }
    __syncthreads();

    for (int kt = 0; kt < 32; ++kt) {
        const int k_next = (kt + 1) << 4;
        if (kt < 31) {
            a0 = *(const float4*)(Aptr + k_next + 0);
            a1 = *(const float4*)(Aptr + k_next + 4);
            b0 = *(const float4*)(Wptr + (size_t)k_next * NG + 0);
            b1 = *(const float4*)(Wptr + (size_t)k_next * NG + 4);
        }

#pragma unroll
        for (int kk = 0; kk < 16; ++kk) {
            float4 av0 = *(const float4*)&As[kk * XS + ty * 8];
            float4 av1 = *(const float4*)&As[kk * XS + ty * 8 + 4];
            float4 bv0 = *(const float4*)&Bs[kk * XS + tx * 8];
            float4 bv1 = *(const float4*)&Bs[kk * XS + tx * 8 + 4];
            float aa[8]  = {av0.x,av0.y,av0.z,av0.w,av1.x,av1.y,av1.z,av1.w};
            float bb2[8] = {bv0.x,bv0.y,bv0.z,bv0.w,bv1.x,bv1.y,bv1.z,bv1.w};
#pragma unroll
            for (int i = 0; i < 8; ++i)
#pragma unroll
                for (int j = 0; j < 8; ++j)
                    acc[i][j] = fmaf(aa[i], bb2[j], acc[i][j]);
        }

        if (kt < 31) {
            __syncthreads();
            float av[8] = {a0.x,a0.y,a0.z,a0.w,a1.x,a1.y,a1.z,a1.w};
#pragma unroll
            for (int j = 0; j < 8; ++j) As[(akq + j) * XS + arow] = av[j];
            *(float4*)&Bs[bk * XS + bn]     = b0;
            *(float4*)&Bs[bk * XS + bn + 4] = b1;
            __syncthreads();
        }
    }

    float* __restrict__ Cd = g_xg + (size_t)dir * BB * TT * NG;
    const int nbase = n0 + tx * 8;
    float4 bi0 = *(const float4*)(bias + nbase);
    float4 bi1 = *(const float4*)(bias + nbase + 4);
#pragma unroll
    for (int i = 0; i < 8; ++i) {
        const int m = m0 + ty * 8 + i;
        float4 o0, o1;
        o0.x = acc[i][0] + bi0.x; o0.y = acc[i][1] + bi0.y;
        o0.z = acc[i][2] + bi0.z; o0.w = acc[i][3] + bi0.w;
        o1.x = acc[i][4] + bi1.x; o1.y = acc[i][5] + bi1.y;
        o1.z = acc[i][6] + bi1.z; o1.w = acc[i][7] + bi1.w;
        *(float4*)&Cd[(size_t)m * NG + nbase]     = o0;
        *(float4*)&Cd[(size_t)m * NG + nbase + 4] = o1;
    }
}

// ---------------------------------------------------------------------------
// Software grid barrier: per-direction (64 blocks), monotonic generation.
// ---------------------------------------------------------------------------
__device__ __forceinline__ void grid_bar(int dir, int tid, unsigned& bar_t)
{
    __threadfence();
    __syncthreads();
    if (tid == 0) {
        ++bar_t;
        unsigned arrived = atomicAdd(&g_cnt[dir], 1u) + 1u;
        if (arrived == 64u) {
            atomicExch(&g_cnt[dir], 0u);
            __threadfence();
            atomicExch(&g_gen[dir], bar_t);
        } else {
            while ((int)(*(volatile unsigned*)&g_gen[dir] - bar_t) < 0) { }
            __threadfence();
        }
    }
    __syncthreads();
}

// ---------------------------------------------------------------------------
// Phase 2: persistent scan. 128 blocks x 256 threads. Block = (dir, 8 cols).
// Thread = (batch b, column c); full K=512 in-register, packed f32x2 FMA.
// h / rh loaded in ONE high-MLP burst (16 LDG.128/thread) + single sync.
// smem floats: weights 3*8*516 = 12384 | sH 4 quarter-planes * 32*132 = 16896
// total 29280 floats = 117,120 B  (1 block/SM)
// ---------------------------------------------------------------------------
#define SWS 516          // weight row stride  (floats)
#define CHS 132          // h row stride within a quarter-plane (floats)
#define QPL (BB * CHS)   // quarter-plane size
#define SCAN_SMEM_FLOATS (3 * 8 * SWS + 4 * QPL)
#define SCAN_SMEM_BYTES  (SCAN_SMEM_FLOATS * 4)

__global__ void __launch_bounds__(256, 1)
scan_kernel(const float* __restrict__ Uf,
            const float* __restrict__ Ub,
            float* __restrict__ out)
{
    extern __shared__ float sm[];
    float* sWz = sm;                     // [c][u]  c*516 + u
    float* sWr = sWz + 8 * SWS;
    float* sWh = sWr + 8 * SWS;
    float* sH  = sWh + 8 * SWS;          // [q][b][u&127] : q*QPL + b*CHS + ...

    const int tid   = threadIdx.x;
    const int dir   = blockIdx.x >> 6;
    const int cg    = blockIdx.x & 63;
    const int hbase = cg << 3;
    const float* __restrict__ Urec = dir ? Ub : Uf;

    for (int i = tid; i < 4096; i += 256) {
        const int u  = i >> 3;
        const int cc = i & 7;
        const size_t src = (size_t)u * NG + hbase + cc;
        sWz[cc * SWS + u] = Urec[src];
        sWr[cc * SWS + u] = Urec[src + UU];
        sWh[cc * SWS + u] = Urec[src + 2 * UU];
    }

    unsigned bar_t = 0;
    if (tid == 0) bar_t = *(volatile unsigned*)&g_gen[dir];

    const int b = tid >> 3;              // 0..31
    const int c = tid & 7;               // 0..7
    const int j = hbase + c;

    const size_t xg_base = (size_t)dir * BB * TT + (size_t)b * TT;
    const int    rh_base = (dir * BB) << 9;
    const size_t out_col = (size_t)dir * UU;

    const ulonglong2* __restrict__ wz2 = (const ulonglong2*)(sWz + c * SWS);
    const ulonglong2* __restrict__ wr2 = (const ulonglong2*)(sWr + c * SWS);
    const ulonglong2* __restrict__ wh2 = (const ulonglong2*)(sWh + c * SWS);

    __syncthreads();

    for (int s = 0; s < TT; ++s) {
        const int t_x = dir ? (TT - 1 - s) : s;
        const float* __restrict__ xrow = g_xg + (xg_base + t_x) * NG;
        const float xz = xrow[j];
        const float xr = xrow[UU + j];
        const float xh = xrow[2 * UU + j];
        float hp = 0.0f;
        if (s > 0)
            hp = __ldcg(out + ((size_t)b * TT + (s - 1)) * OC + out_col + j);

        // ---- load full h_prev -> sH, single high-MLP burst ----
        if (s == 0) {
            for (int i = tid; i < 4 * QPL; i += 256) sH[i] = 0.0f;
        } else {
            const float* __restrict__ hsrc =
                out + (size_t)(s - 1) * OC + out_col;
            float4 t0[8], t1[8];
#pragma unroll
            for (int r = 0; r < 8; ++r) {
                const int i = tid + (r << 8);
                t0[r] = __ldcg((const float4*)(hsrc +
                         (size_t)(i >> 7) * TT * OC + ((i & 127) << 2)));
            }
#pragma unroll
            for (int r = 0; r < 8; ++r) {
                const int i = tid + ((r + 8) << 8);
                t1[r] = __ldcg((const float4*)(hsrc +
                         (size_t)(i >> 7) * TT * OC + ((i & 127) << 2)));
            }
#pragma unroll
            for (int r = 0; r < 8; ++r) {
                const int i  = tid + (r << 8);
                const int u4 = (i & 127) << 2;
                *(float4*)&sH[(u4 >> 7) * QPL + (i >> 7) * CHS + (u4 & 127)] = t0[r];
            }
#pragma unroll
            for (int r = 0; r < 8; ++r) {
                const int i  = tid + ((r + 8) << 8);
                const int u4 = (i & 127) << 2;
                *(float4*)&sH[(u4 >> 7) * QPL + (i >> 7) * CHS + (u4 & 127)] = t1[r];
            }
        }
        __syncthreads();

        // ---- phase A: z/r gates, packed f32x2 FMA ----
        unsigned long long az0 = 0ull, az1 = 0ull, ar0 = 0ull, ar1 = 0ull;
#pragma unroll
        for (int q = 0; q < 4; ++q) {
            const ulonglong2* __restrict__ hq =
                (const ulonglong2*)(sH + q * QPL + b * CHS);
            const ulonglong2* __restrict__ wzq = wz2 + (q << 5);
            const ulonglong2* __restrict__ wrq = wr2 + (q << 5);
#pragma unroll 8
            for (int uu = 0; uu < 32; ++uu) {
                ulonglong2 hv = hq[uu];
                ulonglong2 w1 = wzq[uu];
                ulonglong2 w2 = wrq[uu];
                FMA2(az0, hv.x, w1.x); FMA2(az1, hv.y, w1.y);
                FMA2(ar0, hv.x, w2.x); FMA2(ar1, hv.y, w2.y);
            }
        }

        float rz, rzh;
        {
            const float z = hsig(xz + pair_sum(az0) + pair_sum(az1));
            const float r = hsig(xr + pair_sum(ar0) + pair_sum(ar1));
            rz  = z;
            rzh = z * hp;
            __stcg(&g_rh[rh_base + (b << 9) + j], r * hp);
        }
        grid_bar(dir, tid, bar_t);

        // ---- load rh -> sH, single burst ----
        {
            const float* __restrict__ rsrc = g_rh + rh_base;
            float4 t0[8], t1[8];
#pragma unroll
            for (int r = 0; r < 8; ++r)
                t0[r] = __ldcg((const float4*)(rsrc + ((tid + (r << 8)) << 2)));
#pragma unroll
            for (int r = 0; r < 8; ++r)
                t1[r] = __ldcg((const float4*)(rsrc + ((tid + ((r + 8) << 8)) << 2)));
#pragma unroll
            for (int r = 0; r < 8; ++r) {
                const int i  = tid + (r << 8);
                const int u4 = (i & 127) << 2;
                *(float4*)&sH[(u4 >> 7) * QPL + (i >> 7) * CHS + (u4 & 127)] = t0[r];
            }
#pragma unroll
            for (int r = 0; r < 8; ++r) {
                const int i  = tid + ((r + 8) << 8);
                const int u4 = (i & 127) << 2;
                *(float4*)&sH[(u4 >> 7) * QPL + (i >> 7) * CHS + (u4 & 127)] = t1[r];
            }
        }
        __syncthreads();

        // ---- phase B: candidate GEMM over rh ----
        unsigned long long ah0 = 0ull, ah1 = 0ull;
#pragma unroll
        for (int q = 0; q < 4; ++q) {
            const ulonglong2* __restrict__ hq =
                (const ulonglong2*)(sH + q * QPL + b * CHS);
            const ulonglong2* __restrict__ whq = wh2 + (q << 5);
#pragma unroll 8
            for (int uu = 0; uu < 32; ++uu) {
                ulonglong2 hv = hq[uu];
                ulonglong2 w1 = whq[uu];
                FMA2(ah0, hv.x, w1.x); FMA2(ah1, hv.y, w1.y);
            }
        }

        {
            const float cand = tanhf(xh + pair_sum(ah0) + pair_sum(ah1));
            const float hnew = rzh + (1.0f - rz) * cand;
            __stcg(&out[((size_t)b * TT + s) * OC + out_col + j], hnew);
        }
        grid_bar(dir, tid, bar_t);
    }
}

// ---------------------------------------------------------------------------
extern "C" void kernel_launch(void* const* d_in, const int* in_sizes, int n_in,
                              void* d_out, int out_size)
{
    (void)in_sizes; (void)n_in; (void)out_size;
    const float* x  = (const float*)d_in[0];
    const float* Wf = (const float*)d_in[1];
    const float* Uf = (const float*)d_in[2];
    const float* bf = (const float*)d_in[3];
    const float* Wb = (const float*)d_in[4];
    const float* Ub = (const float*)d_in[5];
    const float* bb = (const float*)d_in[6];
    float* out = (float*)d_out;

    cudaFuncSetAttribute(scan_kernel,
                         cudaFuncAttributeMaxDynamicSharedMemorySize,
                         SCAN_SMEM_BYTES);

    dim3 g1(NG / 128, (BB * TT) / 128, 2);   // 12 x 128 x 2
    xgemm_kernel<<<g1, 256>>>(x, Wf, bf, Wb, bb);

    scan_kernel<<<128, 256, SCAN_SMEM_BYTES>>>(Uf, Ub, out);
}